// round 16
// baseline (speedup 1.0000x reference)
#include <cuda_runtime.h>
#include <cstdint>
#include <cstddef>

// Problem constants
#define NN 100000
#define EE 600000
#define DD 128

// ---------------- scratch ----------------
__device__ float g_Q   [(size_t)NN * DD];
__device__ float g_K   [(size_t)NN * DD];
__device__ float g_V   [(size_t)NN * DD];
__device__ float g_SKIP[(size_t)NN * DD];
__device__ float g_AGG [(size_t)NN * DD];
__device__ float g_H   [(size_t)NN * DD];
__device__ float g_den [(size_t)NN * 8];
__device__ int   g_is64;

// ---------------- tf32 helpers ----------------
__device__ __forceinline__ uint32_t f2tf32(float v) {
    uint32_t r;
    asm("cvt.rna.tf32.f32 %0, %1;" : "=r"(r) : "f"(v));
    return r;
}
__device__ __forceinline__ void mma_tf32(float& d0, float& d1, float& d2, float& d3,
                                         uint32_t a0, uint32_t a1, uint32_t a2, uint32_t a3,
                                         uint32_t b0, uint32_t b1) {
    asm volatile(
        "mma.sync.aligned.m16n8k8.row.col.f32.tf32.tf32.f32 "
        "{%0,%1,%2,%3}, {%4,%5,%6,%7}, {%8,%9}, {%0,%1,%2,%3};"
        : "+f"(d0), "+f"(d1), "+f"(d2), "+f"(d3)
        : "r"(a0), "r"(a1), "r"(a2), "r"(a3), "r"(b0), "r"(b1));
}

#define AS_STRIDE 132
#define WS_STRIDE 136
#define AS_ELEMS  (64 * AS_STRIDE)                 // 8448
#define WS_ELEMS  (128 * WS_STRIDE)                // 17408
#define GEMM_SMEM ((AS_ELEMS + WS_ELEMS) * 4)      // 103424 -> 2 CTAs/SM
#define FFN_SMEM  GEMM_SMEM
#define FUSED_SMEM (GEMM_SMEM + 64 * 2 * 4)

#define TPC 8   // 64-edge tiles per CTA in fused edge kernel

__device__ __forceinline__ int load_idx(const void* p, long long i, int is64) {
    if (is64) return (int)((const long long*)p)[i];
    return ((const int*)p)[i];
}

// ---------------- node projections, 512 threads; also zeroes AGG/den ----------------
__global__ void __launch_bounds__(512, 2)
proj_kernel(const float* __restrict__ A, int M,
            const float* Wg0, const float* Wg1, const float* Wg2, const float* Wg3,
            const float* bg0, const float* bg1, const float* bg2, const float* bg3,
            float* og0, float* og1, float* og2, float* og3,
            float* __restrict__ AGG, float* __restrict__ den) {
    extern __shared__ uint32_t sm[];
    uint32_t* As = sm;
    uint32_t* Ws = sm + AS_ELEMS;

    int tid = threadIdx.x;
    int wid = tid >> 5;
    int lane = tid & 31;
    int row0 = blockIdx.x * 64;

    const float* Wp[4] = {Wg0, Wg1, Wg2, Wg3};
    const float* Bp[4] = {bg0, bg1, bg2, bg3};
    float*       Op[4] = {og0, og1, og2, og3};

    // zero this block's AGG rows + den entries
    {
        float4 z = make_float4(0.f, 0.f, 0.f, 0.f);
#pragma unroll
        for (int it = 0; it < 4; it++) {
            int idx = it * 512 + tid;
            int r = idx >> 5, c4 = idx & 31;
            if (row0 + r < M) ((float4*)(AGG + (size_t)(row0 + r) * DD))[c4] = z;
        }
        int r = tid >> 3, hh = tid & 7;
        if (row0 + r < M) den[(size_t)(row0 + r) * 8 + hh] = 0.f;
    }

    // stage A tile
#pragma unroll
    for (int it = 0; it < 4; it++) {
        int idx = it * 512 + tid;
        int r = idx >> 5, c4 = idx & 31;
        float4 v = make_float4(0.f, 0.f, 0.f, 0.f);
        if (row0 + r < M) v = ((const float4*)(A + (size_t)(row0 + r) * DD))[c4];
        uint4 t = make_uint4(f2tf32(v.x), f2tf32(v.y), f2tf32(v.z), f2tf32(v.w));
        *(uint4*)&As[r * AS_STRIDE + c4 * 4] = t;
    }

    int wr = wid & 3, wc = wid >> 2;
    int qid = lane >> 2, qln = lane & 3;

    for (int w = 0; w < 4; w++) {
        __syncthreads();
        const float* Wgp = Wp[w];
#pragma unroll
        for (int it = 0; it < 8; it++) {
            int idx = it * 512 + tid;
            int k = idx >> 5, c4 = idx & 31;
            float4 v = ((const float4*)(Wgp + (size_t)k * DD))[c4];
            uint4 t = make_uint4(f2tf32(v.x), f2tf32(v.y), f2tf32(v.z), f2tf32(v.w));
            *(uint4*)&Ws[k * WS_STRIDE + c4 * 4] = t;
        }
        __syncthreads();

        float acc[4][4];
#pragma unroll
        for (int nt = 0; nt < 4; nt++)
#pragma unroll
            for (int j = 0; j < 4; j++) acc[nt][j] = 0.f;

#pragma unroll
        for (int ks = 0; ks < 16; ks++) {
            int k0 = ks * 8;
            const uint32_t* ap = &As[(wr * 16 + qid) * AS_STRIDE + k0 + qln];
            uint32_t a0 = ap[0];
            uint32_t a2 = ap[4];
            uint32_t a1 = ap[8 * AS_STRIDE];
            uint32_t a3 = ap[8 * AS_STRIDE + 4];
#pragma unroll
            for (int nt = 0; nt < 4; nt++) {
                int n0 = wc * 32 + nt * 8;
                uint32_t b0 = Ws[(k0 + qln) * WS_STRIDE + n0 + qid];
                uint32_t b1 = Ws[(k0 + 4 + qln) * WS_STRIDE + n0 + qid];
                mma_tf32(acc[nt][0], acc[nt][1], acc[nt][2], acc[nt][3],
                         a0, a1, a2, a3, b0, b1);
            }
        }

        const float* bias = Bp[w];
        float* outp = Op[w];
#pragma unroll
        for (int nt = 0; nt < 4; nt++) {
            int col = wc * 32 + nt * 8 + qln * 2;
            float b0v = bias[col], b1v = bias[col + 1];
            int r = row0 + wr * 16 + qid;
            if (r < M)
                *(float2*)&outp[(size_t)r * DD + col] =
                    make_float2(acc[nt][0] + b0v, acc[nt][1] + b1v);
            if (r + 8 < M)
                *(float2*)&outp[(size_t)(r + 8) * DD + col] =
                    make_float2(acc[nt][2] + b0v, acc[nt][3] + b1v);
        }
    }
}

// ---------------- FUSED: edge GEMM + attention, 512 threads, next-tile prefetch ----------------
__global__ void __launch_bounds__(512, 2)
fused_edge_kernel(const float* __restrict__ EA, const float* __restrict__ We,
                  const float* __restrict__ Q, const float* __restrict__ K,
                  const float* __restrict__ V, const void* __restrict__ eidx,
                  int E, float* __restrict__ denom, float* __restrict__ AGG) {
    extern __shared__ uint32_t sm[];
    uint32_t* Ws  = sm;                         // [128][WS_STRIDE]
    uint32_t* As  = sm + WS_ELEMS;              // [64][AS_STRIDE], reused as Ef
    int* ssrc = (int*)(sm + WS_ELEMS + AS_ELEMS);
    int* sdst = ssrc + 64;

    int tid = threadIdx.x;
    int wid = tid >> 5;
    int lane = tid & 31;
    int is64 = g_is64;

    // stage We once
#pragma unroll
    for (int it = 0; it < 8; it++) {
        int idx = it * 512 + tid;
        int k = idx >> 5, c4 = idx & 31;
        float4 v = ((const float4*)(We + (size_t)k * DD))[c4];
        uint4 t = make_uint4(f2tf32(v.x), f2tf32(v.y), f2tf32(v.z), f2tf32(v.w));
        *(uint4*)&Ws[k * WS_STRIDE + c4 * 4] = t;
    }

    int wr = wid & 3;
    int wc = wid >> 2;
    int qid = lane >> 2, qln = lane & 3;

    int ntiles = (E + 63) >> 6;
    int tbeg = blockIdx.x * TPC;
    int t_end = tbeg + TPC;
    if (t_end > ntiles) t_end = ntiles;

    // prefetch geometry: this lane covers edge (wid*4 + lane>>3) of a tile,
    // 128B line (lane&3) of each of its q/k/v rows.
    int ple  = wid * 4 + (lane >> 3);
    int part = (lane & 3) * 32;

    // prologue: prefetch first tile's gather rows (indices straight from global)
    if (tbeg < t_end) {
        long long ee = (long long)(tbeg << 6) + ple;
        if (ee < E) {
            int psrc = load_idx(eidx, ee, is64);
            int pdst = load_idx(eidx, (long long)E + ee, is64);
            asm volatile("prefetch.global.L2 [%0];" :: "l"(Q + (size_t)pdst * DD + part));
            asm volatile("prefetch.global.L2 [%0];" :: "l"(K + (size_t)psrc * DD + part));
            asm volatile("prefetch.global.L2 [%0];" :: "l"(V + (size_t)psrc * DD + part));
        }
    }

    for (int t = tbeg; t < t_end; t++) {
        int e0 = t << 6;
        __syncthreads();

        // stage edge_attr tile (tf32)
#pragma unroll
        for (int it = 0; it < 4; it++) {
            int idx = it * 512 + tid;
            int r = idx >> 5, c4 = idx & 31;
            float4 v = make_float4(0.f, 0.f, 0.f, 0.f);
            if (e0 + r < E) v = ((const float4*)(EA + (size_t)(e0 + r) * DD))[c4];
            uint4 tt = make_uint4(f2tf32(v.x), f2tf32(v.y), f2tf32(v.z), f2tf32(v.w));
            *(uint4*)&As[r * AS_STRIDE + c4 * 4] = tt;
        }
        if (tid < 64) {
            long long ee = (long long)(e0 + tid);
            int ok = (e0 + tid) < E;
            ssrc[tid] = ok ? load_idx(eidx, ee, is64) : 0;
            sdst[tid] = ok ? load_idx(eidx, (long long)E + ee, is64) : 0;
        }
        __syncthreads();

        // prefetch NEXT tile's q/k/v gather rows (indices from global) — one
        // full tile iteration of distance before consumption.
        if (t + 1 < t_end) {
            long long ee = (long long)((t + 1) << 6) + ple;
            if (ee < E) {
                int psrc = load_idx(eidx, ee, is64);
                int pdst = load_idx(eidx, (long long)E + ee, is64);
                asm volatile("prefetch.global.L2 [%0];" :: "l"(Q + (size_t)pdst * DD + part));
                asm volatile("prefetch.global.L2 [%0];" :: "l"(K + (size_t)psrc * DD + part));
                asm volatile("prefetch.global.L2 [%0];" :: "l"(V + (size_t)psrc * DD + part));
            }
        }

        // MMA: Ef_tile[64,128] = A_tile @ We
        float acc[4][4];
#pragma unroll
        for (int nt = 0; nt < 4; nt++)
#pragma unroll
            for (int j = 0; j < 4; j++) acc[nt][j] = 0.f;

#pragma unroll
        for (int ks = 0; ks < 16; ks++) {
            int k0 = ks * 8;
            const uint32_t* ap = &As[(wr * 16 + qid) * AS_STRIDE + k0 + qln];
            uint32_t a0 = ap[0];
            uint32_t a2 = ap[4];
            uint32_t a1 = ap[8 * AS_STRIDE];
            uint32_t a3 = ap[8 * AS_STRIDE + 4];
#pragma unroll
            for (int nt = 0; nt < 4; nt++) {
                int n0 = wc * 32 + nt * 8;
                uint32_t b0 = Ws[(k0 + qln) * WS_STRIDE + n0 + qid];
                uint32_t b1 = Ws[(k0 + 4 + qln) * WS_STRIDE + n0 + qid];
                mma_tf32(acc[nt][0], acc[nt][1], acc[nt][2], acc[nt][3],
                         a0, a1, a2, a3, b0, b1);
            }
        }
        __syncthreads();

        // Ef tile -> smem (f32, reuse As)
        float* Es = (float*)As;
#pragma unroll
        for (int nt = 0; nt < 4; nt++) {
            int col = wc * 32 + nt * 8 + qln * 2;
            int r = wr * 16 + qid;
            *(float2*)&Es[r * AS_STRIDE + col] =
                make_float2(acc[nt][0], acc[nt][1]);
            *(float2*)&Es[(r + 8) * AS_STRIDE + col] =
                make_float2(acc[nt][2], acc[nt][3]);
        }
        __syncthreads();

        // attention: warp wid handles edges e0 + wid*4 .. +3
        for (int i = 0; i < 4; i++) {
            int le = wid * 4 + i;
            bool ok = (e0 + le) < E;
            int src = ssrc[le], dst = sdst[le];

            float4 e4 = *(const float4*)&Es[le * AS_STRIDE + lane * 4];
            float4 q4 = *(const float4*)&Q[(size_t)dst * DD + lane * 4];
            float4 k4 = *(const float4*)&K[(size_t)src * DD + lane * 4];

            float p = q4.x * (k4.x + e4.x) + q4.y * (k4.y + e4.y) +
                      q4.z * (k4.z + e4.z) + q4.w * (k4.w + e4.w);
            p += __shfl_xor_sync(0xffffffffu, p, 1);
            p += __shfl_xor_sync(0xffffffffu, p, 2);

            float ex = expf(p * 0.25f);
            float4 v4 = *(const float4*)&V[(size_t)src * DD + lane * 4];
            if (ok) {
                if ((lane & 3) == 0)
                    atomicAdd(&denom[(size_t)dst * 8 + (lane >> 2)], ex);
                float m0 = ex * (v4.x + e4.x);
                float m1 = ex * (v4.y + e4.y);
                float m2 = ex * (v4.z + e4.z);
                float m3 = ex * (v4.w + e4.w);
                float* o = &AGG[(size_t)dst * DD + lane * 4];
                asm volatile("red.global.add.v4.f32 [%0], {%1,%2,%3,%4};"
                             :: "l"(o), "f"(m0), "f"(m1), "f"(m2), "f"(m3) : "memory");
            }
        }
    }
}

// ---------------- FUSED FFN + first LN, 512 threads (R12 proven) ----------------
__global__ void __launch_bounds__(512, 2)
ffn_kernel(const float* __restrict__ x, const float* __restrict__ AGG,
           const float* __restrict__ SKIP, const float* __restrict__ den,
           const float* __restrict__ g1, const float* __restrict__ be1,
           float* __restrict__ H,
           const float* __restrict__ W1, const float* __restrict__ b1,
           const float* __restrict__ W2, const float* __restrict__ b2,
           const float* __restrict__ g2, const float* __restrict__ be2,
           float* __restrict__ outp, int M) {
    extern __shared__ uint32_t sm[];
    uint32_t* As = sm;
    uint32_t* Ws = sm + AS_ELEMS;

    int tid = threadIdx.x;
    int wid = tid >> 5;
    int lane = tid & 31;
    int row0 = blockIdx.x * 64;

    // ---- prologue: h = x + LN1(AGG/den + SKIP)
#pragma unroll
    for (int i = 0; i < 4; i++) {
        int r = wid * 4 + i;
        int row = row0 + r;
        float4 o = make_float4(0.f, 0.f, 0.f, 0.f);
        float4 xx = o;
        if (row < M) {
            float dh = den[(size_t)row * 8 + (lane >> 2)];
            float inv = 1.0f / (dh + 1e-16f);
            o  = *(const float4*)&AGG[(size_t)row * DD + lane * 4];
            float4 s = *(const float4*)&SKIP[(size_t)row * DD + lane * 4];
            o.x = o.x * inv + s.x;
            o.y = o.y * inv + s.y;
            o.z = o.z * inv + s.z;
            o.w = o.w * inv + s.w;
            xx = *(const float4*)&x[(size_t)row * DD + lane * 4];
        }
        float sum = o.x + o.y + o.z + o.w;
#pragma unroll
        for (int off = 16; off >= 1; off >>= 1)
            sum += __shfl_xor_sync(0xffffffffu, sum, off);
        float mu = sum * (1.0f / 128.0f);
        float dx = o.x - mu, dy = o.y - mu, dz = o.z - mu, dw = o.w - mu;
        float ss = dx * dx + dy * dy + dz * dz + dw * dw;
#pragma unroll
        for (int off = 16; off >= 1; off >>= 1)
            ss += __shfl_xor_sync(0xffffffffu, ss, off);
        float rs = rsqrtf(ss * (1.0f / 128.0f) + 1e-5f);

        float4 gg = *(const float4*)&g1[lane * 4];
        float4 bb = *(const float4*)&be1[lane * 4];
        float4 h4;
        h4.x = xx.x + dx * rs * gg.x + bb.x;
        h4.y = xx.y + dy * rs * gg.y + bb.y;
        h4.z = xx.z + dz * rs * gg.z + bb.z;
        h4.w = xx.w + dw * rs * gg.w + bb.w;

        if (row < M)
            *(float4*)&H[(size_t)row * DD + lane * 4] = h4;
        uint4 t = make_uint4(f2tf32(h4.x), f2tf32(h4.y), f2tf32(h4.z), f2tf32(h4.w));
        *(uint4*)&As[r * AS_STRIDE + lane * 4] = t;
    }
    // stage W1
#pragma unroll
    for (int it = 0; it < 8; it++) {
        int idx = it * 512 + tid;
        int k = idx >> 5, c4 = idx & 31;
        float4 v = ((const float4*)(W1 + (size_t)k * DD))[c4];
        uint4 t = make_uint4(f2tf32(v.x), f2tf32(v.y), f2tf32(v.z), f2tf32(v.w));
        *(uint4*)&Ws[k * WS_STRIDE + c4 * 4] = t;
    }
    __syncthreads();

    int wr = wid & 3, wc = wid >> 2;
    int qid = lane >> 2, qln = lane & 3;

    // ---- MMA 1: T = h @ W1 ----
    float acc[4][4];
#pragma unroll
    for (int nt = 0; nt < 4; nt++)
#pragma unroll
        for (int j = 0; j < 4; j++) acc[nt][j] = 0.f;

#pragma unroll
    for (int ks = 0; ks < 16; ks++) {
        int k0 = ks * 8;
        const uint32_t* ap = &As[(wr * 16 + qid) * AS_STRIDE + k0 + qln];
        uint32_t a0 = ap[0];
        uint32_t a2 = ap[4];
        uint32_t a1 = ap[8 * AS_STRIDE];
        uint32_t a3 = ap[8 * AS_STRIDE + 4];
#pragma unroll
        for (int nt = 0; nt < 4; nt++) {
            int n0 = wc * 32 + nt * 8;
            uint32_t b0 = Ws[(k0 + qln) * WS_STRIDE + n0 + qid];
            uint32_t b1v = Ws[(k0 + 4 + qln) * WS_STRIDE + n0 + qid];
            mma_tf32(acc[nt][0], acc[nt][1], acc[nt][2], acc[nt][3],
                     a0, a1, a2, a3, b0, b1v);
        }
    }
    __syncthreads();

    // T1 = silu(acc + b1) -> As (tf32); stage W2 -> Ws
#pragma unroll
    for (int nt = 0; nt < 4; nt++) {
        int col = wc * 32 + nt * 8 + qln * 2;
        float c0 = b1[col], c1 = b1[col + 1];
        int r = wr * 16 + qid;
        float o0 = acc[nt][0] + c0;
        float o1 = acc[nt][1] + c1;
        float o2 = acc[nt][2] + c0;
        float o3 = acc[nt][3] + c1;
        o0 = o0 / (1.f + expf(-o0));
        o1 = o1 / (1.f + expf(-o1));
        o2 = o2 / (1.f + expf(-o2));
        o3 = o3 / (1.f + expf(-o3));
        As[r * AS_STRIDE + col]           = f2tf32(o0);
        As[r * AS_STRIDE + col + 1]       = f2tf32(o1);
        As[(r + 8) * AS_STRIDE + col]     = f2tf32(o2);
        As[(r + 8) * AS_STRIDE + col + 1] = f2tf32(o3);
    }
#pragma unroll
    for (int it = 0; it < 8; it++) {
        int idx = it * 512 + tid;
        int k = idx >> 5, c4 = idx & 31;
        float4 v = ((const float4*)(W2 + (size_t)k * DD))[c4];
        uint4 t = make_uint4(f2tf32(v.x), f2tf32(v.y), f2tf32(v.z), f2tf32(v.w));
        *(uint4*)&Ws[k * WS_STRIDE + c4 * 4] = t;
    }
    __syncthreads();

    // ---- MMA 2: F = T1 @ W2 ----
#pragma unroll
    for (int nt = 0; nt < 4; nt++)
#pragma unroll
        for (int j = 0; j < 4; j++) acc[nt][j] = 0.f;

#pragma unroll
    for (int ks = 0; ks < 16; ks++) {
        int k0 = ks * 8;
        const uint32_t* ap = &As[(wr * 16 + qid) * AS_STRIDE + k0 + qln];
        uint32_t a0 = ap[0];
        uint32_t a2 = ap[4];
        uint32_t a1 = ap[8 * AS_STRIDE];
        uint32_t a3 = ap[8 * AS_STRIDE + 4];
#pragma unroll
        for (int nt = 0; nt < 4; nt++) {
            int n0 = wc * 32 + nt * 8;
            uint32_t b0 = Ws[(k0 + qln) * WS_STRIDE + n0 + qid];
            uint32_t b1v = Ws[(k0 + 4 + qln) * WS_STRIDE + n0 + qid];
            mma_tf32(acc[nt][0], acc[nt][1], acc[nt][2], acc[nt][3],
                     a0, a1, a2, a3, b0, b1v);
        }
    }
    __syncthreads();

    // F2 tile (+b2) -> Ws smem (f32)
    float* Es = (float*)Ws;
#pragma unroll
    for (int nt = 0; nt < 4; nt++) {
        int col = wc * 32 + nt * 8 + qln * 2;
        float c0 = b2[col], c1 = b2[col + 1];
        int r = wr * 16 + qid;
        *(float2*)&Es[r * AS_STRIDE + col] =
            make_float2(acc[nt][0] + c0, acc[nt][1] + c1);
        *(float2*)&Es[(r + 8) * AS_STRIDE + col] =
            make_float2(acc[nt][2] + c0, acc[nt][3] + c1);
    }
    __syncthreads();

    // LN2 + residual
#pragma unroll
    for (int i = 0; i < 4; i++) {
        int r = wid * 4 + i;
        float4 o = *(float4*)&Es[r * AS_STRIDE + lane * 4];

        float sum = o.x + o.y + o.z + o.w;
#pragma unroll
        for (int off = 16; off >= 1; off >>= 1)
            sum += __shfl_xor_sync(0xffffffffu, sum, off);
        float mu = sum * (1.0f / 128.0f);

        float dx = o.x - mu, dy = o.y - mu, dz = o.z - mu, dw = o.w - mu;
        float ss = dx * dx + dy * dy + dz * dz + dw * dw;
#pragma unroll
        for (int off = 16; off >= 1; off >>= 1)
            ss += __shfl_xor_sync(0xffffffffu, ss, off);
        float rs = rsqrtf(ss * (1.0f / 128.0f) + 1e-5f);

        if (row0 + r < M) {
            float4 gg = *(const float4*)&g2[lane * 4];
            float4 bb = *(const float4*)&be2[lane * 4];
            float4 hh = *(const float4*)&H[(size_t)(row0 + r) * DD + lane * 4];
            float4 rr;
            rr.x = hh.x + dx * rs * gg.x + bb.x;
            rr.y = hh.y + dy * rs * gg.y + bb.y;
            rr.z = hh.z + dz * rs * gg.z + bb.z;
            rr.w = hh.w + dw * rs * gg.w + bb.w;
            *(float4*)&outp[(size_t)(row0 + r) * DD + lane * 4] = rr;
        }
    }
}

// ---------------- edge index dtype detection ----------------
__global__ void detect_idx_kernel(const long long* __restrict__ p, int E, int N) {
    if (threadIdx.x == 0 && blockIdx.x == 0) {
        int ok64 = 1;
        int n = (E < 64) ? E : 64;
        for (int i = 0; i < n; i++) {
            long long v = p[i];
            if (v < 0 || v >= (long long)N) { ok64 = 0; break; }
        }
        g_is64 = ok64;
    }
}

// ---------------- launch ----------------
extern "C" void kernel_launch(void* const* d_in, const int* in_sizes, int n_in,
                              void* d_out, int out_size) {
    const void*  eidx      = d_in[0];
    const float* x         = (const float*)d_in[1];
    const float* edge_attr = (const float*)d_in[2];
    const float* Wq = (const float*)d_in[3],  *bq = (const float*)d_in[4];
    const float* Wk = (const float*)d_in[5],  *bk = (const float*)d_in[6];
    const float* Wv = (const float*)d_in[7],  *bv = (const float*)d_in[8];
    const float* We = (const float*)d_in[9];
    const float* Wskip = (const float*)d_in[10], *bskip = (const float*)d_in[11];
    const float* W1 = (const float*)d_in[12], *b1 = (const float*)d_in[13];
    const float* W2 = (const float*)d_in[14], *b2 = (const float*)d_in[15];
    const float* g1 = (const float*)d_in[16], *be1 = (const float*)d_in[17];
    const float* g2 = (const float*)d_in[18], *be2 = (const float*)d_in[19];
    float* out = (float*)d_out;

    int N = in_sizes[1] / DD;   // 100000
    int E = in_sizes[2] / DD;   // 600000

    float *pQ, *pK, *pV, *pSK, *pAGG, *pH, *pDen;
    cudaGetSymbolAddress((void**)&pQ,   g_Q);
    cudaGetSymbolAddress((void**)&pK,   g_K);
    cudaGetSymbolAddress((void**)&pV,   g_V);
    cudaGetSymbolAddress((void**)&pSK,  g_SKIP);
    cudaGetSymbolAddress((void**)&pAGG, g_AGG);
    cudaGetSymbolAddress((void**)&pH,   g_H);
    cudaGetSymbolAddress((void**)&pDen, g_den);

    cudaFuncSetAttribute(proj_kernel, cudaFuncAttributeMaxDynamicSharedMemorySize,
                         GEMM_SMEM);
    cudaFuncSetAttribute(fused_edge_kernel, cudaFuncAttributeMaxDynamicSharedMemorySize,
                         FUSED_SMEM);
    cudaFuncSetAttribute(ffn_kernel, cudaFuncAttributeMaxDynamicSharedMemorySize,
                         FFN_SMEM);

    detect_idx_kernel<<<1, 32>>>((const long long*)eidx, E, N);

    // node projections (512 threads) + AGG/den zeroing
    int nb_node = (N + 63) / 64;
    proj_kernel<<<nb_node, 512, GEMM_SMEM>>>(x, N,
        Wq, Wk, Wv, Wskip, bq, bk, bv, bskip, pQ, pK, pV, pSK, pAGG, pDen);

    // fused edge GEMM + attention (512 threads, next-tile prefetch)
    int ntiles = (E + 63) / 64;
    int nb_fused = (ntiles + TPC - 1) / TPC;
    fused_edge_kernel<<<nb_fused, 512, FUSED_SMEM>>>(edge_attr, We, pQ, pK, pV,
                                                     eidx, E, pDen, pAGG);

    // fused: h = x + LN1(AGG/den + skip); out = h + LN2(FFN(h))
    ffn_kernel<<<nb_node, 512, FFN_SMEM>>>(x, pAGG, pSK, pDen, g1, be1, pH,
                                           W1, b1, W2, b2, g2, be2, out, N);
}

// round 17
// speedup vs baseline: 1.0548x; 1.0548x over previous
#include <cuda_runtime.h>
#include <cstdint>
#include <cstddef>

// Problem constants
#define NN 100000
#define EE 600000
#define DD 128

// ---------------- scratch ----------------
__device__ float g_Q   [(size_t)NN * DD];
__device__ float g_K   [(size_t)NN * DD];
__device__ float g_V   [(size_t)NN * DD];
__device__ float g_AGG [(size_t)NN * DD];
__device__ float g_H   [(size_t)NN * DD];
__device__ float g_den [(size_t)NN * 8];
__device__ int   g_is64;

// ---------------- tf32 helpers ----------------
__device__ __forceinline__ uint32_t f2tf32(float v) {
    uint32_t r;
    asm("cvt.rna.tf32.f32 %0, %1;" : "=r"(r) : "f"(v));
    return r;
}
__device__ __forceinline__ void mma_tf32(float& d0, float& d1, float& d2, float& d3,
                                         uint32_t a0, uint32_t a1, uint32_t a2, uint32_t a3,
                                         uint32_t b0, uint32_t b1) {
    asm volatile(
        "mma.sync.aligned.m16n8k8.row.col.f32.tf32.tf32.f32 "
        "{%0,%1,%2,%3}, {%4,%5,%6,%7}, {%8,%9}, {%0,%1,%2,%3};"
        : "+f"(d0), "+f"(d1), "+f"(d2), "+f"(d3)
        : "r"(a0), "r"(a1), "r"(a2), "r"(a3), "r"(b0), "r"(b1));
}

#define AS_STRIDE 132
#define WS_STRIDE 136
#define AS_ELEMS  (64 * AS_STRIDE)                 // 8448
#define WS_ELEMS  (128 * WS_STRIDE)                // 17408
#define GEMM_SMEM ((AS_ELEMS + WS_ELEMS) * 4)      // 103424 -> 2 CTAs/SM
#define FFN_SMEM  GEMM_SMEM
#define FUSED_SMEM (GEMM_SMEM + 64 * 2 * 4)

#define TPC 8   // 64-edge tiles per CTA in fused edge kernel

__device__ __forceinline__ int load_idx(const void* p, long long i, int is64) {
    if (is64) return (int)((const long long*)p)[i];
    return ((const int*)p)[i];
}

// ---------------- node projections (Q,K,V), 512 threads; also zeroes AGG/den ----------------
__global__ void __launch_bounds__(512, 2)
proj_kernel(const float* __restrict__ A, int M,
            const float* Wg0, const float* Wg1, const float* Wg2,
            const float* bg0, const float* bg1, const float* bg2,
            float* og0, float* og1, float* og2,
            float* __restrict__ AGG, float* __restrict__ den) {
    extern __shared__ uint32_t sm[];
    uint32_t* As = sm;
    uint32_t* Ws = sm + AS_ELEMS;

    int tid = threadIdx.x;
    int wid = tid >> 5;
    int lane = tid & 31;
    int row0 = blockIdx.x * 64;

    const float* Wp[3] = {Wg0, Wg1, Wg2};
    const float* Bp[3] = {bg0, bg1, bg2};
    float*       Op[3] = {og0, og1, og2};

    // zero this block's AGG rows + den entries
    {
        float4 z = make_float4(0.f, 0.f, 0.f, 0.f);
#pragma unroll
        for (int it = 0; it < 4; it++) {
            int idx = it * 512 + tid;
            int r = idx >> 5, c4 = idx & 31;
            if (row0 + r < M) ((float4*)(AGG + (size_t)(row0 + r) * DD))[c4] = z;
        }
        int r = tid >> 3, hh = tid & 7;
        if (row0 + r < M) den[(size_t)(row0 + r) * 8 + hh] = 0.f;
    }

    // stage A tile
#pragma unroll
    for (int it = 0; it < 4; it++) {
        int idx = it * 512 + tid;
        int r = idx >> 5, c4 = idx & 31;
        float4 v = make_float4(0.f, 0.f, 0.f, 0.f);
        if (row0 + r < M) v = ((const float4*)(A + (size_t)(row0 + r) * DD))[c4];
        uint4 t = make_uint4(f2tf32(v.x), f2tf32(v.y), f2tf32(v.z), f2tf32(v.w));
        *(uint4*)&As[r * AS_STRIDE + c4 * 4] = t;
    }

    int wr = wid & 3, wc = wid >> 2;
    int qid = lane >> 2, qln = lane & 3;

    for (int w = 0; w < 3; w++) {
        __syncthreads();
        const float* Wgp = Wp[w];
#pragma unroll
        for (int it = 0; it < 8; it++) {
            int idx = it * 512 + tid;
            int k = idx >> 5, c4 = idx & 31;
            float4 v = ((const float4*)(Wgp + (size_t)k * DD))[c4];
            uint4 t = make_uint4(f2tf32(v.x), f2tf32(v.y), f2tf32(v.z), f2tf32(v.w));
            *(uint4*)&Ws[k * WS_STRIDE + c4 * 4] = t;
        }
        __syncthreads();

        float acc[4][4];
#pragma unroll
        for (int nt = 0; nt < 4; nt++)
#pragma unroll
            for (int j = 0; j < 4; j++) acc[nt][j] = 0.f;

#pragma unroll
        for (int ks = 0; ks < 16; ks++) {
            int k0 = ks * 8;
            const uint32_t* ap = &As[(wr * 16 + qid) * AS_STRIDE + k0 + qln];
            uint32_t a0 = ap[0];
            uint32_t a2 = ap[4];
            uint32_t a1 = ap[8 * AS_STRIDE];
            uint32_t a3 = ap[8 * AS_STRIDE + 4];
#pragma unroll
            for (int nt = 0; nt < 4; nt++) {
                int n0 = wc * 32 + nt * 8;
                uint32_t b0 = Ws[(k0 + qln) * WS_STRIDE + n0 + qid];
                uint32_t b1 = Ws[(k0 + 4 + qln) * WS_STRIDE + n0 + qid];
                mma_tf32(acc[nt][0], acc[nt][1], acc[nt][2], acc[nt][3],
                         a0, a1, a2, a3, b0, b1);
            }
        }

        const float* bias = Bp[w];
        float* outp = Op[w];
#pragma unroll
        for (int nt = 0; nt < 4; nt++) {
            int col = wc * 32 + nt * 8 + qln * 2;
            float b0v = bias[col], b1v = bias[col + 1];
            int r = row0 + wr * 16 + qid;
            if (r < M)
                *(float2*)&outp[(size_t)r * DD + col] =
                    make_float2(acc[nt][0] + b0v, acc[nt][1] + b1v);
            if (r + 8 < M)
                *(float2*)&outp[(size_t)(r + 8) * DD + col] =
                    make_float2(acc[nt][2] + b0v, acc[nt][3] + b1v);
        }
    }
}

// ---------------- FUSED: edge GEMM + attention, 512 threads (R12 proven) ----------------
__global__ void __launch_bounds__(512, 2)
fused_edge_kernel(const float* __restrict__ EA, const float* __restrict__ We,
                  const float* __restrict__ Q, const float* __restrict__ K,
                  const float* __restrict__ V, const void* __restrict__ eidx,
                  int E, float* __restrict__ denom, float* __restrict__ AGG) {
    extern __shared__ uint32_t sm[];
    uint32_t* Ws  = sm;                         // [128][WS_STRIDE]
    uint32_t* As  = sm + WS_ELEMS;              // [64][AS_STRIDE], reused as Ef
    int* ssrc = (int*)(sm + WS_ELEMS + AS_ELEMS);
    int* sdst = ssrc + 64;

    int tid = threadIdx.x;
    int wid = tid >> 5;
    int lane = tid & 31;
    int is64 = g_is64;

    // stage We once
#pragma unroll
    for (int it = 0; it < 8; it++) {
        int idx = it * 512 + tid;
        int k = idx >> 5, c4 = idx & 31;
        float4 v = ((const float4*)(We + (size_t)k * DD))[c4];
        uint4 t = make_uint4(f2tf32(v.x), f2tf32(v.y), f2tf32(v.z), f2tf32(v.w));
        *(uint4*)&Ws[k * WS_STRIDE + c4 * 4] = t;
    }

    int wr = wid & 3;
    int wc = wid >> 2;
    int qid = lane >> 2, qln = lane & 3;

    int ntiles = (E + 63) >> 6;
    int t_end = blockIdx.x * TPC + TPC;
    if (t_end > ntiles) t_end = ntiles;

    for (int t = blockIdx.x * TPC; t < t_end; t++) {
        int e0 = t << 6;
        __syncthreads();

        // stage edge_attr tile (tf32)
#pragma unroll
        for (int it = 0; it < 4; it++) {
            int idx = it * 512 + tid;
            int r = idx >> 5, c4 = idx & 31;
            float4 v = make_float4(0.f, 0.f, 0.f, 0.f);
            if (e0 + r < E) v = ((const float4*)(EA + (size_t)(e0 + r) * DD))[c4];
            uint4 tt = make_uint4(f2tf32(v.x), f2tf32(v.y), f2tf32(v.z), f2tf32(v.w));
            *(uint4*)&As[r * AS_STRIDE + c4 * 4] = tt;
        }
        if (tid < 64) {
            long long ee = (long long)(e0 + tid);
            int ok = (e0 + tid) < E;
            ssrc[tid] = ok ? load_idx(eidx, ee, is64) : 0;
            sdst[tid] = ok ? load_idx(eidx, (long long)E + ee, is64) : 0;
        }
        __syncthreads();

        // L2 prefetch of this tile's q/k/v gather rows (R9/R12 proven timing)
        {
            int le   = wid * 4 + (lane >> 3);
            int part = (lane & 3) * 32;
            int psrc = ssrc[le], pdst = sdst[le];
            const float* qb = Q + (size_t)pdst * DD + part;
            const float* kb = K + (size_t)psrc * DD + part;
            const float* vb = V + (size_t)psrc * DD + part;
            asm volatile("prefetch.global.L2 [%0];" :: "l"(qb));
            asm volatile("prefetch.global.L2 [%0];" :: "l"(kb));
            asm volatile("prefetch.global.L2 [%0];" :: "l"(vb));
        }

        // MMA: Ef_tile[64,128] = A_tile @ We
        float acc[4][4];
#pragma unroll
        for (int nt = 0; nt < 4; nt++)
#pragma unroll
            for (int j = 0; j < 4; j++) acc[nt][j] = 0.f;

#pragma unroll
        for (int ks = 0; ks < 16; ks++) {
            int k0 = ks * 8;
            const uint32_t* ap = &As[(wr * 16 + qid) * AS_STRIDE + k0 + qln];
            uint32_t a0 = ap[0];
            uint32_t a2 = ap[4];
            uint32_t a1 = ap[8 * AS_STRIDE];
            uint32_t a3 = ap[8 * AS_STRIDE + 4];
#pragma unroll
            for (int nt = 0; nt < 4; nt++) {
                int n0 = wc * 32 + nt * 8;
                uint32_t b0 = Ws[(k0 + qln) * WS_STRIDE + n0 + qid];
                uint32_t b1 = Ws[(k0 + 4 + qln) * WS_STRIDE + n0 + qid];
                mma_tf32(acc[nt][0], acc[nt][1], acc[nt][2], acc[nt][3],
                         a0, a1, a2, a3, b0, b1);
            }
        }
        __syncthreads();

        // Ef tile -> smem (f32, reuse As)
        float* Es = (float*)As;
#pragma unroll
        for (int nt = 0; nt < 4; nt++) {
            int col = wc * 32 + nt * 8 + qln * 2;
            int r = wr * 16 + qid;
            *(float2*)&Es[r * AS_STRIDE + col] =
                make_float2(acc[nt][0], acc[nt][1]);
            *(float2*)&Es[(r + 8) * AS_STRIDE + col] =
                make_float2(acc[nt][2], acc[nt][3]);
        }
        __syncthreads();

        // attention: warp wid handles edges e0 + wid*4 .. +3
        for (int i = 0; i < 4; i++) {
            int le = wid * 4 + i;
            bool ok = (e0 + le) < E;
            int src = ssrc[le], dst = sdst[le];

            float4 e4 = *(const float4*)&Es[le * AS_STRIDE + lane * 4];
            float4 q4 = *(const float4*)&Q[(size_t)dst * DD + lane * 4];
            float4 k4 = *(const float4*)&K[(size_t)src * DD + lane * 4];

            float p = q4.x * (k4.x + e4.x) + q4.y * (k4.y + e4.y) +
                      q4.z * (k4.z + e4.z) + q4.w * (k4.w + e4.w);
            p += __shfl_xor_sync(0xffffffffu, p, 1);
            p += __shfl_xor_sync(0xffffffffu, p, 2);

            float ex = expf(p * 0.25f);
            float4 v4 = *(const float4*)&V[(size_t)src * DD + lane * 4];
            if (ok) {
                if ((lane & 3) == 0)
                    atomicAdd(&denom[(size_t)dst * 8 + (lane >> 2)], ex);
                float m0 = ex * (v4.x + e4.x);
                float m1 = ex * (v4.y + e4.y);
                float m2 = ex * (v4.z + e4.z);
                float m3 = ex * (v4.w + e4.w);
                float* o = &AGG[(size_t)dst * DD + lane * 4];
                asm volatile("red.global.add.v4.f32 [%0], {%1,%2,%3,%4};"
                             :: "l"(o), "f"(m0), "f"(m1), "f"(m2), "f"(m3) : "memory");
            }
        }
    }
}

// ---------------- FUSED: skip GEMM + LN1 + FFN + LN2, 512 threads ----------------
// 1. skip = x @ Wskip + bskip   (tf32 MMA, x staged in smem)
// 2. h = x + LN1(AGG/den + skip); h -> global H (f32) and smem As (tf32)
// 3. out = h + LN2(silu(h@W1+b1)@W2 + b2)
__global__ void __launch_bounds__(512, 2)
ffn_kernel(const float* __restrict__ x, const float* __restrict__ AGG,
           const float* __restrict__ den,
           const float* __restrict__ Wskip, const float* __restrict__ bskip,
           const float* __restrict__ g1, const float* __restrict__ be1,
           float* __restrict__ H,
           const float* __restrict__ W1, const float* __restrict__ b1,
           const float* __restrict__ W2, const float* __restrict__ b2,
           const float* __restrict__ g2, const float* __restrict__ be2,
           float* __restrict__ outp, int M) {
    extern __shared__ uint32_t sm[];
    uint32_t* As = sm;
    uint32_t* Ws = sm + AS_ELEMS;
    float* Es = (float*)Ws;     // f32 view of Ws for skip/F2 tiles

    int tid = threadIdx.x;
    int wid = tid >> 5;
    int lane = tid & 31;
    int row0 = blockIdx.x * 64;

    int wr = wid & 3, wc = wid >> 2;
    int qid = lane >> 2, qln = lane & 3;

    // ---- stage x tile (tf32) + Wskip ----
#pragma unroll
    for (int it = 0; it < 4; it++) {
        int idx = it * 512 + tid;
        int r = idx >> 5, c4 = idx & 31;
        float4 v = make_float4(0.f, 0.f, 0.f, 0.f);
        if (row0 + r < M) v = ((const float4*)(x + (size_t)(row0 + r) * DD))[c4];
        uint4 t = make_uint4(f2tf32(v.x), f2tf32(v.y), f2tf32(v.z), f2tf32(v.w));
        *(uint4*)&As[r * AS_STRIDE + c4 * 4] = t;
    }
#pragma unroll
    for (int it = 0; it < 8; it++) {
        int idx = it * 512 + tid;
        int k = idx >> 5, c4 = idx & 31;
        float4 v = ((const float4*)(Wskip + (size_t)k * DD))[c4];
        uint4 t = make_uint4(f2tf32(v.x), f2tf32(v.y), f2tf32(v.z), f2tf32(v.w));
        *(uint4*)&Ws[k * WS_STRIDE + c4 * 4] = t;
    }
    __syncthreads();

    // ---- MMA 0: S = x @ Wskip ----
    float acc[4][4];
#pragma unroll
    for (int nt = 0; nt < 4; nt++)
#pragma unroll
        for (int j = 0; j < 4; j++) acc[nt][j] = 0.f;

#pragma unroll
    for (int ks = 0; ks < 16; ks++) {
        int k0 = ks * 8;
        const uint32_t* ap = &As[(wr * 16 + qid) * AS_STRIDE + k0 + qln];
        uint32_t a0 = ap[0];
        uint32_t a2 = ap[4];
        uint32_t a1 = ap[8 * AS_STRIDE];
        uint32_t a3 = ap[8 * AS_STRIDE + 4];
#pragma unroll
        for (int nt = 0; nt < 4; nt++) {
            int n0 = wc * 32 + nt * 8;
            uint32_t b0 = Ws[(k0 + qln) * WS_STRIDE + n0 + qid];
            uint32_t b1v = Ws[(k0 + 4 + qln) * WS_STRIDE + n0 + qid];
            mma_tf32(acc[nt][0], acc[nt][1], acc[nt][2], acc[nt][3],
                     a0, a1, a2, a3, b0, b1v);
        }
    }
    __syncthreads();   // Ws reads done

    // S (+bskip) -> Es smem (f32, stride AS_STRIDE)
#pragma unroll
    for (int nt = 0; nt < 4; nt++) {
        int col = wc * 32 + nt * 8 + qln * 2;
        float c0 = bskip[col], c1 = bskip[col + 1];
        int r = wr * 16 + qid;
        *(float2*)&Es[r * AS_STRIDE + col] =
            make_float2(acc[nt][0] + c0, acc[nt][1] + c1);
        *(float2*)&Es[(r + 8) * AS_STRIDE + col] =
            make_float2(acc[nt][2] + c0, acc[nt][3] + c1);
    }
    __syncthreads();

    // ---- prologue: h = x + LN1(AGG/den + skip); warp wid -> rows wid*4..+3
#pragma unroll
    for (int i = 0; i < 4; i++) {
        int r = wid * 4 + i;
        int row = row0 + r;
        float4 o = make_float4(0.f, 0.f, 0.f, 0.f);
        float4 xx = o;
        if (row < M) {
            float dh = den[(size_t)row * 8 + (lane >> 2)];
            float inv = 1.0f / (dh + 1e-16f);
            o  = *(const float4*)&AGG[(size_t)row * DD + lane * 4];
            float4 s = *(const float4*)&Es[r * AS_STRIDE + lane * 4];
            o.x = o.x * inv + s.x;
            o.y = o.y * inv + s.y;
            o.z = o.z * inv + s.z;
            o.w = o.w * inv + s.w;
            xx = *(const float4*)&x[(size_t)row * DD + lane * 4];
        }
        float sum = o.x + o.y + o.z + o.w;
#pragma unroll
        for (int off = 16; off >= 1; off >>= 1)
            sum += __shfl_xor_sync(0xffffffffu, sum, off);
        float mu = sum * (1.0f / 128.0f);
        float dx = o.x - mu, dy = o.y - mu, dz = o.z - mu, dw = o.w - mu;
        float ss = dx * dx + dy * dy + dz * dz + dw * dw;
#pragma unroll
        for (int off = 16; off >= 1; off >>= 1)
            ss += __shfl_xor_sync(0xffffffffu, ss, off);
        float rs = rsqrtf(ss * (1.0f / 128.0f) + 1e-5f);

        float4 gg = *(const float4*)&g1[lane * 4];
        float4 bb = *(const float4*)&be1[lane * 4];
        float4 h4;
        h4.x = xx.x + dx * rs * gg.x + bb.x;
        h4.y = xx.y + dy * rs * gg.y + bb.y;
        h4.z = xx.z + dz * rs * gg.z + bb.z;
        h4.w = xx.w + dw * rs * gg.w + bb.w;

        if (row < M)
            *(float4*)&H[(size_t)row * DD + lane * 4] = h4;
        uint4 t = make_uint4(f2tf32(h4.x), f2tf32(h4.y), f2tf32(h4.z), f2tf32(h4.w));
        *(uint4*)&As[r * AS_STRIDE + lane * 4] = t;   // overwrites x tile (consumed)
    }
    __syncthreads();   // Es (skip) fully consumed; As holds h

    // stage W1
#pragma unroll
    for (int it = 0; it < 8; it++) {
        int idx = it * 512 + tid;
        int k = idx >> 5, c4 = idx & 31;
        float4 v = ((const float4*)(W1 + (size_t)k * DD))[c4];
        uint4 t = make_uint4(f2tf32(v.x), f2tf32(v.y), f2tf32(v.z), f2tf32(v.w));
        *(uint4*)&Ws[k * WS_STRIDE + c4 * 4] = t;
    }
    __syncthreads();

    // ---- MMA 1: T = h @ W1 ----
#pragma unroll
    for (int nt = 0; nt < 4; nt++)
#pragma unroll
        for (int j = 0; j < 4; j++) acc[nt][j] = 0.f;

#pragma unroll
    for (int ks = 0; ks < 16; ks++) {
        int k0 = ks * 8;
        const uint32_t* ap = &As[(wr * 16 + qid) * AS_STRIDE + k0 + qln];
        uint32_t a0 = ap[0];
        uint32_t a2 = ap[4];
        uint32_t a1 = ap[8 * AS_STRIDE];
        uint32_t a3 = ap[8 * AS_STRIDE + 4];
#pragma unroll
        for (int nt = 0; nt < 4; nt++) {
            int n0 = wc * 32 + nt * 8;
            uint32_t b0 = Ws[(k0 + qln) * WS_STRIDE + n0 + qid];
            uint32_t b1v = Ws[(k0 + 4 + qln) * WS_STRIDE + n0 + qid];
            mma_tf32(acc[nt][0], acc[nt][1], acc[nt][2], acc[nt][3],
                     a0, a1, a2, a3, b0, b1v);
        }
    }
    __syncthreads();

    // T1 = silu(acc + b1) -> As (tf32); stage W2 -> Ws
#pragma unroll
    for (int nt = 0; nt < 4; nt++) {
        int col = wc * 32 + nt * 8 + qln * 2;
        float c0 = b1[col], c1 = b1[col + 1];
        int r = wr * 16 + qid;
        float o0 = acc[nt][0] + c0;
        float o1 = acc[nt][1] + c1;
        float o2 = acc[nt][2] + c0;
        float o3 = acc[nt][3] + c1;
        o0 = o0 / (1.f + expf(-o0));
        o1 = o1 / (1.f + expf(-o1));
        o2 = o2 / (1.f + expf(-o2));
        o3 = o3 / (1.f + expf(-o3));
        As[r * AS_STRIDE + col]           = f2tf32(o0);
        As[r * AS_STRIDE + col + 1]       = f2tf32(o1);
        As[(r + 8) * AS_STRIDE + col]     = f2tf32(o2);
        As[(r + 8) * AS_STRIDE + col + 1] = f2tf32(o3);
    }
#pragma unroll
    for (int it = 0; it < 8; it++) {
        int idx = it * 512 + tid;
        int k = idx >> 5, c4 = idx & 31;
        float4 v = ((const float4*)(W2 + (size_t)k * DD))[c4];
        uint4 t = make_uint4(f2tf32(v.x), f2tf32(v.y), f2tf32(v.z), f2tf32(v.w));
        *(uint4*)&Ws[k * WS_STRIDE + c4 * 4] = t;
    }
    __syncthreads();

    // ---- MMA 2: F = T1 @ W2 ----
#pragma unroll
    for (int nt = 0; nt < 4; nt++)
#pragma unroll
        for (int j = 0; j < 4; j++) acc[nt][j] = 0.f;

#pragma unroll
    for (int ks = 0; ks < 16; ks++) {
        int k0 = ks * 8;
        const uint32_t* ap = &As[(wr * 16 + qid) * AS_STRIDE + k0 + qln];
        uint32_t a0 = ap[0];
        uint32_t a2 = ap[4];
        uint32_t a1 = ap[8 * AS_STRIDE];
        uint32_t a3 = ap[8 * AS_STRIDE + 4];
#pragma unroll
        for (int nt = 0; nt < 4; nt++) {
            int n0 = wc * 32 + nt * 8;
            uint32_t b0 = Ws[(k0 + qln) * WS_STRIDE + n0 + qid];
            uint32_t b1v = Ws[(k0 + 4 + qln) * WS_STRIDE + n0 + qid];
            mma_tf32(acc[nt][0], acc[nt][1], acc[nt][2], acc[nt][3],
                     a0, a1, a2, a3, b0, b1v);
        }
    }
    __syncthreads();

    // F2 tile (+b2) -> Es smem (f32)
#pragma unroll
    for (int nt = 0; nt < 4; nt++) {
        int col = wc * 32 + nt * 8 + qln * 2;
        float c0 = b2[col], c1 = b2[col + 1];
        int r = wr * 16 + qid;
        *(float2*)&Es[r * AS_STRIDE + col] =
            make_float2(acc[nt][0] + c0, acc[nt][1] + c1);
        *(float2*)&Es[(r + 8) * AS_STRIDE + col] =
            make_float2(acc[nt][2] + c0, acc[nt][3] + c1);
    }
    __syncthreads();

    // LN2 + residual
#pragma unroll
    for (int i = 0; i < 4; i++) {
        int r = wid * 4 + i;
        float4 o = *(float4*)&Es[r * AS_STRIDE + lane * 4];

        float sum = o.x + o.y + o.z + o.w;
#pragma unroll
        for (int off = 16; off >= 1; off >>= 1)
            sum += __shfl_xor_sync(0xffffffffu, sum, off);
        float mu = sum * (1.0f / 128.0f);

        float dx = o.x - mu, dy = o.y - mu, dz = o.z - mu, dw = o.w - mu;
        float ss = dx * dx + dy * dy + dz * dz + dw * dw;
#pragma unroll
        for (int off = 16; off >= 1; off >>= 1)
            ss += __shfl_xor_sync(0xffffffffu, ss, off);
        float rs = rsqrtf(ss * (1.0f / 128.0f) + 1e-5f);

        if (row0 + r < M) {
            float4 gg = *(const float4*)&g2[lane * 4];
            float4 bb = *(const float4*)&be2[lane * 4];
            float4 hh = *(const float4*)&H[(size_t)(row0 + r) * DD + lane * 4];
            float4 rr;
            rr.x = hh.x + dx * rs * gg.x + bb.x;
            rr.y = hh.y + dy * rs * gg.y + bb.y;
            rr.z = hh.z + dz * rs * gg.z + bb.z;
            rr.w = hh.w + dw * rs * gg.w + bb.w;
            *(float4*)&outp[(size_t)(row0 + r) * DD + lane * 4] = rr;
        }
    }
}

// ---------------- edge index dtype detection ----------------
__global__ void detect_idx_kernel(const long long* __restrict__ p, int E, int N) {
    if (threadIdx.x == 0 && blockIdx.x == 0) {
        int ok64 = 1;
        int n = (E < 64) ? E : 64;
        for (int i = 0; i < n; i++) {
            long long v = p[i];
            if (v < 0 || v >= (long long)N) { ok64 = 0; break; }
        }
        g_is64 = ok64;
    }
}

// ---------------- launch ----------------
extern "C" void kernel_launch(void* const* d_in, const int* in_sizes, int n_in,
                              void* d_out, int out_size) {
    const void*  eidx      = d_in[0];
    const float* x         = (const float*)d_in[1];
    const float* edge_attr = (const float*)d_in[2];
    const float* Wq = (const float*)d_in[3],  *bq = (const float*)d_in[4];
    const float* Wk = (const float*)d_in[5],  *bk = (const float*)d_in[6];
    const float* Wv = (const float*)d_in[7],  *bv = (const float*)d_in[8];
    const float* We = (const float*)d_in[9];
    const float* Wskip = (const float*)d_in[10], *bskip = (const float*)d_in[11];
    const float* W1 = (const float*)d_in[12], *b1 = (const float*)d_in[13];
    const float* W2 = (const float*)d_in[14], *b2 = (const float*)d_in[15];
    const float* g1 = (const float*)d_in[16], *be1 = (const float*)d_in[17];
    const float* g2 = (const float*)d_in[18], *be2 = (const float*)d_in[19];
    float* out = (float*)d_out;

    int N = in_sizes[1] / DD;   // 100000
    int E = in_sizes[2] / DD;   // 600000

    float *pQ, *pK, *pV, *pAGG, *pH, *pDen;
    cudaGetSymbolAddress((void**)&pQ,   g_Q);
    cudaGetSymbolAddress((void**)&pK,   g_K);
    cudaGetSymbolAddress((void**)&pV,   g_V);
    cudaGetSymbolAddress((void**)&pAGG, g_AGG);
    cudaGetSymbolAddress((void**)&pH,   g_H);
    cudaGetSymbolAddress((void**)&pDen, g_den);

    cudaFuncSetAttribute(proj_kernel, cudaFuncAttributeMaxDynamicSharedMemorySize,
                         GEMM_SMEM);
    cudaFuncSetAttribute(fused_edge_kernel, cudaFuncAttributeMaxDynamicSharedMemorySize,
                         FUSED_SMEM);
    cudaFuncSetAttribute(ffn_kernel, cudaFuncAttributeMaxDynamicSharedMemorySize,
                         FFN_SMEM);

    detect_idx_kernel<<<1, 32>>>((const long long*)eidx, E, N);

    // node projections Q,K,V (512 threads) + AGG/den zeroing
    int nb_node = (N + 63) / 64;
    proj_kernel<<<nb_node, 512, GEMM_SMEM>>>(x, N,
        Wq, Wk, Wv, bq, bk, bv, pQ, pK, pV, pAGG, pDen);

    // fused edge GEMM + attention (512 threads, same-tile prefetch)
    int ntiles = (E + 63) / 64;
    int nb_fused = (ntiles + TPC - 1) / TPC;
    fused_edge_kernel<<<nb_fused, 512, FUSED_SMEM>>>(edge_attr, We, pQ, pK, pV,
                                                     eidx, E, pDen, pAGG);

    // fused: skip = x@Wskip+bskip; h = x + LN1(AGG/den + skip); out = h + LN2(FFN(h))
    ffn_kernel<<<nb_node, 512, FFN_SMEM>>>(x, pAGG, pDen, Wskip, bskip,
                                           g1, be1, pH,
                                           W1, b1, W2, b2, g2, be2, out, N);
}